// round 8
// baseline (speedup 1.0000x reference)
#include <cuda_runtime.h>
#include <math.h>
#include <stdint.h>

// NT-Xent R8: int8 IMMA m16n8k32 (2x MAC/instruction vs fp16 m16n8k16; the
// legacy-mma issue rate is the measured bottleneck). Normalized rows quantized
// to s8*127; exact fp32 positive logits; int32 accumulate (noise-free);
// diagonal exclusion cancels exactly. Upper-triangle 128x128 tiles (2080),
// persistent 148 CTAs x 512 threads, 2-deep cp.async pipeline.

#define TWO_N   8192
#define N_HALF  4096
#define CDIM    128
#define NBLK    64
#define TILES   2080                         // 64*65/2
#define GRID    148
#define INV_T   14.285714285714286f
#define K1      20.60984248218323f           // INV_T * log2(e)
#define K2      (K1 / 16129.0f)              // dequant (1/127^2) folded in

#define TSTRIDE 144                          // 128B row + 16B pad (conflict-free)
#define TILEB   (128 * TSTRIDE)              // 18432
#define OFF_A0  0
#define OFF_A1  TILEB
#define OFF_B0  (2 * TILEB)
#define OFF_B1  (3 * TILEB)
#define OFF_RED (4 * TILEB)                  // 73728
#define SMEM_DYN (OFF_RED + 128 * 9 * 4 + 128 * 2 * 4)

__device__ __align__(16) uint32_t g_Fq[TWO_N * 32];   // s8x4 packed, 128B rows
__device__ float g_part[NBLK * NBLK * 128];
__device__ float g_pos[TWO_N];
__device__ double g_bsum[32];
__device__ int g_ctr;

__device__ __forceinline__ uint32_t smem_u32(const void* p) {
    uint32_t a;
    asm("{ .reg .u64 t; cvta.to.shared.u64 t, %1; cvt.u32.u64 %0, t; }"
        : "=r"(a) : "l"(p));
    return a;
}
__device__ __forceinline__ float ex2f(float x) {
    float r;
    asm("ex2.approx.ftz.f32 %0, %1;" : "=f"(r) : "f"(x));
    return r;
}
__device__ __forceinline__ void cp16(uint32_t s, const void* g) {
    asm volatile("cp.async.cg.shared.global [%0], [%1], 16;" :: "r"(s), "l"(g));
}
#define CP_COMMIT() asm volatile("cp.async.commit_group;" ::: "memory")
#define CP_WAIT1()  asm volatile("cp.async.wait_group 1;" ::: "memory")
#define CP_WAIT0()  asm volatile("cp.async.wait_group 0;" ::: "memory")

#define LDSM_X4(r0, r1, r2, r3, addr)                                          \
    asm volatile("ldmatrix.sync.aligned.m8n8.x4.shared.b16 {%0,%1,%2,%3},[%4];"\
        : "=r"(r0), "=r"(r1), "=r"(r2), "=r"(r3) : "r"(addr))

#define IMMA16832(c, a0, a1, a2, a3, b0, b1)                                   \
    asm volatile("mma.sync.aligned.m16n8k32.row.col.s32.s8.s8.s32 "            \
        "{%0,%1,%2,%3},{%4,%5,%6,%7},{%8,%9},{%0,%1,%2,%3};"                   \
        : "+r"((c)[0]), "+r"((c)[1]), "+r"((c)[2]), "+r"((c)[3])               \
        : "r"(a0), "r"(a1), "r"(a2), "r"(a3), "r"(b0), "r"(b1))

// ---------------------------------------------------------------------------
// Kernel 1: normalize -> s8 quantize (x127) + exact fp32 positive logits.
// One warp per pair i (rows i and i+N).
// ---------------------------------------------------------------------------
__global__ void __launch_bounds__(256) normalize_kernel(
        const float* __restrict__ f1, const float* __restrict__ f2) {
    int wid  = threadIdx.x >> 5;
    int lane = threadIdx.x & 31;
    int i    = blockIdx.x * 8 + wid;

    float4 a = *(const float4*)(f1 + (size_t)i * CDIM + lane * 4);
    float4 b = *(const float4*)(f2 + (size_t)i * CDIM + lane * 4);
    float s1 = a.x * a.x + a.y * a.y + a.z * a.z + a.w * a.w;
    float s2 = b.x * b.x + b.y * b.y + b.z * b.z + b.w * b.w;
    float d  = a.x * b.x + a.y * b.y + a.z * b.z + a.w * b.w;
    #pragma unroll
    for (int o = 16; o; o >>= 1) {
        s1 += __shfl_xor_sync(0xffffffffu, s1, o);
        s2 += __shfl_xor_sync(0xffffffffu, s2, o);
        d  += __shfl_xor_sync(0xffffffffu, d,  o);
    }
    float i1 = 127.0f / fmaxf(sqrtf(s1), 1e-12f);
    float i2 = 127.0f / fmaxf(sqrtf(s2), 1e-12f);

    int q0 = __float2int_rn(a.x * i1), q1 = __float2int_rn(a.y * i1);
    int q2 = __float2int_rn(a.z * i1), q3 = __float2int_rn(a.w * i1);
    g_Fq[(size_t)i * 32 + lane] =
        (q0 & 255) | ((q1 & 255) << 8) | ((q2 & 255) << 16) | ((q3 & 255) << 24);

    q0 = __float2int_rn(b.x * i2); q1 = __float2int_rn(b.y * i2);
    q2 = __float2int_rn(b.z * i2); q3 = __float2int_rn(b.w * i2);
    g_Fq[(size_t)(i + N_HALF) * 32 + lane] =
        (q0 & 255) | ((q1 & 255) << 8) | ((q2 & 255) << 16) | ((q3 & 255) << 24);

    if (lane == 0) {
        float pos = (d / (sqrtf(s1) * sqrtf(s2)) - 1.0f) * INV_T;  // exact
        g_pos[i] = pos;
        g_pos[i + N_HALF] = pos;
    }
}

// ---------------------------------------------------------------------------
// Kernel 2: IMMA main. 148 persistent CTAs x 512 thr = 16 warps.
// CTA tile 128x128. Warp (wm=wid&1, wn=wid>>1): rows wm*64+[0,64),
// cols wn*16+[0,16). Warp tile 64x16, 4 K-steps of k32.
// ---------------------------------------------------------------------------
extern __shared__ char dynsmem[];

__global__ void __launch_bounds__(512, 1) ntxent_mma_kernel() {
    const int tid  = threadIdx.x;
    const int lane = tid & 31;
    const int wid  = tid >> 5;
    const int wm   = wid & 1;
    const int wn   = wid >> 1;       // 0..7

    uint32_t sb = smem_u32(dynsmem);
    const uint32_t bufA[2] = { sb + OFF_A0, sb + OFF_A1 };
    const uint32_t bufB[2] = { sb + OFF_B0, sb + OFF_B1 };
    float* sRow = (float*)(dynsmem + OFF_RED);   // [128][9]
    float* sCol = sRow + 128 * 9;                // [128][2]

    // A: rows (wm*64 + mi*16 + lane&15), byte (lane>>4)*16 within k-step.
    const uint32_t aSel = (uint32_t)((wm * 64 + (lane & 15)) * TSTRIDE)
                        + (uint32_t)((lane >> 4) * 16);
    // B: x4 covers 2 n-tiles x 2 k-halves: row wn*16 + (lane&7) + (lane>>4)*8,
    // byte ((lane>>3)&1)*16.
    const uint32_t bSel = (uint32_t)((wn * 16 + (lane & 7) + (lane >> 4) * 8) * TSTRIDE)
                        + (uint32_t)(((lane >> 3) & 1) * 16);

    auto mapIJ = [](int k, int& I, int& J) {
        int i = 0, rem = k;
        while (rem >= NBLK - i) { rem -= NBLK - i; i++; }
        I = i; J = i + rem;
    };
    auto issue_tile = [&](int I, int J, int buf) {
        const char* gA = (const char*)(g_Fq + ((size_t)I << 7) * 32);
        const char* gB = (const char*)(g_Fq + ((size_t)J << 7) * 32);
        #pragma unroll
        for (int i = 0; i < 2; i++) {
            int idx = tid + i * 512, r = idx >> 3, c = idx & 7;
            cp16(bufA[buf] + r * TSTRIDE + c * 16, gA + r * 128 + c * 16);
            cp16(bufB[buf] + r * TSTRIDE + c * 16, gB + r * 128 + c * 16);
        }
        CP_COMMIT();
    };

    auto compute_tile = [&](int cur, int I, int J) {
        int acc[4][2][4];
        #pragma unroll
        for (int mi = 0; mi < 4; mi++)
            #pragma unroll
            for (int ni = 0; ni < 2; ni++)
                #pragma unroll
                for (int rg = 0; rg < 4; rg++) acc[mi][ni][rg] = 0;

        const uint32_t aT = bufA[cur] + aSel;
        const uint32_t bT = bufB[cur] + bSel;
        #pragma unroll
        for (int ks = 0; ks < 4; ks++) {
            uint32_t afr[4][4], bfr[4];
            #pragma unroll
            for (int mi = 0; mi < 4; mi++) {
                uint32_t ad = aT + (uint32_t)(mi * 16 * TSTRIDE + ks * 32);
                LDSM_X4(afr[mi][0], afr[mi][1], afr[mi][2], afr[mi][3], ad);
            }
            LDSM_X4(bfr[0], bfr[1], bfr[2], bfr[3],
                    bT + (uint32_t)(ks * 32));
            #pragma unroll
            for (int mi = 0; mi < 4; mi++)
                #pragma unroll
                for (int ni = 0; ni < 2; ni++)
                    IMMA16832(acc[mi][ni],
                              afr[mi][0], afr[mi][1], afr[mi][2], afr[mi][3],
                              bfr[ni * 2], bfr[ni * 2 + 1]);
        }

        // Epilogue: exp((dot/127^2 - 1)/T) = ex2(acc*K2 - K1).
        float pr[8], pc[4];
        #pragma unroll
        for (int h = 0; h < 8; h++) pr[h] = 0.f;
        #pragma unroll
        for (int h = 0; h < 4; h++) pc[h] = 0.f;
        #pragma unroll
        for (int mi = 0; mi < 4; mi++)
            #pragma unroll
            for (int ni = 0; ni < 2; ni++)
                #pragma unroll
                for (int rg = 0; rg < 4; rg++) {
                    float e = ex2f(fmaf((float)acc[mi][ni][rg], K2, -K1));
                    pr[mi * 2 + (rg >> 1)] += e;
                    pc[ni * 2 + (rg & 1)]  += e;
                }

        if (I == J) {   // diagonal exclusion (exact cancel of quantized value)
            #pragma unroll
            for (int mi = 0; mi < 4; mi++)
                #pragma unroll
                for (int ni = 0; ni < 2; ni++)
                    #pragma unroll
                    for (int rg = 0; rg < 4; rg++) {
                        int rT = wm * 64 + mi * 16 + (lane >> 2) + 8 * (rg >> 1);
                        int cB = wn * 16 + ni * 8 + (lane & 3) * 2 + (rg & 1);
                        if (cB == rT) {
                            float e = ex2f(fmaf((float)acc[mi][ni][rg], K2, -K1));
                            pr[mi * 2 + (rg >> 1)] -= e;
                        }
                    }
        }

        // Warp reductions: rows over lane&3; cols over lane>>2.
        #pragma unroll
        for (int h = 0; h < 8; h++) {
            pr[h] += __shfl_xor_sync(0xffffffffu, pr[h], 1);
            pr[h] += __shfl_xor_sync(0xffffffffu, pr[h], 2);
        }
        #pragma unroll
        for (int h = 0; h < 4; h++) {
            pc[h] += __shfl_xor_sync(0xffffffffu, pc[h], 4);
            pc[h] += __shfl_xor_sync(0xffffffffu, pc[h], 8);
            pc[h] += __shfl_xor_sync(0xffffffffu, pc[h], 16);
        }
        if ((lane & 3) == 0) {
            #pragma unroll
            for (int h = 0; h < 8; h++) {
                int r = wm * 64 + (h >> 1) * 16 + (lane >> 2) + 8 * (h & 1);
                sRow[r * 9 + wn] = pr[h];
            }
        }
        if (lane < 4) {
            #pragma unroll
            for (int h = 0; h < 4; h++) {
                int c = wn * 16 + (h >> 1) * 8 + lane * 2 + (h & 1);
                sCol[c * 2 + wm] = pc[h];
            }
        }
        __syncthreads();   // reductions visible; also all reads of buf cur done

        if (tid < 128) {
            float rs = 0.f;
            #pragma unroll
            for (int x = 0; x < 8; x++) rs += sRow[tid * 9 + x];
            g_part[((size_t)I * NBLK + J) * 128 + tid] = rs;
        } else if (tid < 256) {
            int c = tid - 128;
            if (J > I)
                g_part[((size_t)J * NBLK + I) * 128 + c] =
                    sCol[c * 2] + sCol[c * 2 + 1];
        }
    };

    // ---- pipeline (2-deep prefetch) ----
    int k = blockIdx.x;
    if (k >= TILES) return;
    int I, J, In, Jn;
    mapIJ(k, I, J);
    issue_tile(I, J, 0);
    int k1 = k + GRID;
    bool h1 = (k1 < TILES);
    if (h1) { mapIJ(k1, In, Jn); issue_tile(In, Jn, 1); CP_WAIT1(); }
    else    { CP_WAIT0(); }
    __syncthreads();

    int t = 0;
    while (true) {
        int cur = t & 1;
        compute_tile(cur, I, J);
        if (k + GRID >= TILES) break;
        int k2 = k + 2 * GRID;
        int In2 = 0, Jn2 = 0;
        if (k2 < TILES) {
            mapIJ(k2, In2, Jn2);
            issue_tile(In2, Jn2, cur);
            CP_WAIT1();
        } else {
            CP_WAIT0();
        }
        __syncthreads();
        I = In; J = Jn; In = In2; Jn = Jn2;
        k += GRID; t++;
    }
}

// ---------------------------------------------------------------------------
// Kernel 3: row gather -> log_prob -> fused deterministic final sum.
// ---------------------------------------------------------------------------
__global__ void __launch_bounds__(256) reduce_kernel(float* __restrict__ out) {
    __shared__ double sm[256];
    __shared__ int isLast;
    int tid = threadIdx.x;
    int row = blockIdx.x * 256 + tid;
    int R = row >> 7, m = row & 127;
    float s = 0.f;
    #pragma unroll 8
    for (int O = 0; O < NBLK; O++)
        s += g_part[((size_t)R * NBLK + O) * 128 + m];
    sm[tid] = (double)(g_pos[row] - logf(s));
    __syncthreads();
    #pragma unroll
    for (int o = 128; o; o >>= 1) {
        if (tid < o) sm[tid] += sm[tid + o];
        __syncthreads();
    }
    if (tid == 0) {
        g_bsum[blockIdx.x] = sm[0];
        __threadfence();
        int old = atomicAdd(&g_ctr, 1);
        isLast = (old == 31);
    }
    __syncthreads();
    if (isLast && tid == 0) {
        double tot = 0.0;
        #pragma unroll
        for (int i = 0; i < 32; i++) tot += g_bsum[i];
        out[0] = (float)(-tot / (double)TWO_N);
        g_ctr = 0;   // reset for graph replay
    }
}

// ---------------------------------------------------------------------------
extern "C" void kernel_launch(void* const* d_in, const int* in_sizes, int n_in,
                              void* d_out, int out_size) {
    const float* f1 = (const float*)d_in[0];
    const float* f2 = (const float*)d_in[1];
    float* out = (float*)d_out;

    cudaFuncSetAttribute(ntxent_mma_kernel,
                         cudaFuncAttributeMaxDynamicSharedMemorySize, SMEM_DYN);

    normalize_kernel<<<N_HALF / 8, 256>>>(f1, f2);
    ntxent_mma_kernel<<<GRID, 512, SMEM_DYN>>>();
    reduce_kernel<<<32, 256>>>(out);
}

// round 9
// speedup vs baseline: 1.6294x; 1.6294x over previous
#include <cuda_runtime.h>
#include <cuda_fp16.h>
#include <math.h>
#include <stdint.h>

// NT-Xent R9: single fused persistent kernel (148 CTAs x 512 threads).
// Phase A: normalize -> fp16 + exact fp32 positive logits (all CTAs).
// Phase B: R7's fp16 HMMA upper-triangle tile loop (at the measured
//          legacy-mma throughput floor, ~341 MAC/cyc/SM).
// Phase C: row gather -> log_prob -> ordered deterministic final sum.
// Software global barriers (sense counter; all CTAs co-resident).

#define TWO_N   8192
#define N_HALF  4096
#define CDIM    128
#define NBLK    64
#define TILES   1056                         // 256-col-granularity triangle
#define GRID    148
#define INV_T   14.285714285714286f
#define K1      20.60984248218323f           // INV_T * log2(e)

#define TSTRIDE 272
#define A_BYTES (128 * TSTRIDE)
#define B_BYTES (256 * TSTRIDE)
#define OFF_A0  0
#define OFF_A1  A_BYTES
#define OFF_B0  (2 * A_BYTES)
#define OFF_B1  (2 * A_BYTES + B_BYTES)
#define OFF_RED (2 * A_BYTES + 2 * B_BYTES)
#define SMEM_DYN (OFF_RED + 128 * 9 * 4 + 256 * 2 * 4)   // 215552

__device__ __align__(16) __half g_Fh[TWO_N * CDIM];
__device__ float g_part[NBLK * NBLK * 128];
__device__ float g_pos[TWO_N];
__device__ double g_bsum[16];
__device__ int g_ctr;
__device__ int g_sense;
__device__ int g_count;

__device__ __forceinline__ uint32_t smem_u32(const void* p) {
    uint32_t a;
    asm("{ .reg .u64 t; cvta.to.shared.u64 t, %1; cvt.u32.u64 %0, t; }"
        : "=r"(a) : "l"(p));
    return a;
}
__device__ __forceinline__ float ex2f(float x) {
    float r;
    asm("ex2.approx.ftz.f32 %0, %1;" : "=f"(r) : "f"(x));
    return r;
}
__device__ __forceinline__ void cp16(uint32_t s, const void* g) {
    asm volatile("cp.async.cg.shared.global [%0], [%1], 16;" :: "r"(s), "l"(g));
}
#define CP_COMMIT() asm volatile("cp.async.commit_group;" ::: "memory")
#define CP_WAIT1()  asm volatile("cp.async.wait_group 1;" ::: "memory")
#define CP_WAIT0()  asm volatile("cp.async.wait_group 0;" ::: "memory")

#define LDSM_X4(r0, r1, r2, r3, addr)                                          \
    asm volatile("ldmatrix.sync.aligned.m8n8.x4.shared.b16 {%0,%1,%2,%3},[%4];"\
        : "=r"(r0), "=r"(r1), "=r"(r2), "=r"(r3) : "r"(addr))

#define MMA16816H(c, a, b0, b1)                                                \
    asm volatile("mma.sync.aligned.m16n8k16.row.col.f16.f16.f16.f16 "          \
        "{%0,%1},{%2,%3,%4,%5},{%6,%7},{%0,%1};"                               \
        : "+r"((c)[0]), "+r"((c)[1])                                           \
        : "r"((a)[0]), "r"((a)[1]), "r"((a)[2]), "r"((a)[3]),                  \
          "r"(b0), "r"(b1))

// Global barrier: all GRID CTAs arrive; releaser resets count then bumps sense.
__device__ __forceinline__ void gbar(int tid, int& target) {
    __syncthreads();
    if (tid == 0) {
        __threadfence();
        if (atomicAdd(&g_count, 1) == GRID - 1) {
            g_count = 0;
            __threadfence();
            atomicAdd(&g_sense, 1);
        } else {
            while (((volatile int*)&g_sense)[0] - target < 0) {}
            __threadfence();
        }
    }
    __syncthreads();
    target++;
}

extern __shared__ char dynsmem[];

__global__ void __launch_bounds__(512, 1) ntxent_fused_kernel(
        const float* __restrict__ f1, const float* __restrict__ f2,
        float* __restrict__ out) {
    const int tid  = threadIdx.x;
    const int lane = tid & 31;
    const int wid  = tid >> 5;
    const int wm   = wid & 1;
    const int wn   = wid >> 1;       // 0..7
    const int bx   = blockIdx.x;

    int target;
    if (tid == 0) target = ((volatile int*)&g_sense)[0];
    target = __shfl_sync(0xffffffffu, target, 0) + 1;
    // broadcast to all warps via shared
    __shared__ int sTgt;
    if (tid == 0) sTgt = target;
    __syncthreads();
    target = sTgt;

    // ---------------- Phase A: normalize + pos logits ----------------
    for (int i = bx * 16 + wid; i < N_HALF; i += GRID * 16) {
        float4 a = *(const float4*)(f1 + (size_t)i * CDIM + lane * 4);
        float4 b = *(const float4*)(f2 + (size_t)i * CDIM + lane * 4);
        float s1 = a.x * a.x + a.y * a.y + a.z * a.z + a.w * a.w;
        float s2 = b.x * b.x + b.y * b.y + b.z * b.z + b.w * b.w;
        float d  = a.x * b.x + a.y * b.y + a.z * b.z + a.w * b.w;
        #pragma unroll
        for (int o = 16; o; o >>= 1) {
            s1 += __shfl_xor_sync(0xffffffffu, s1, o);
            s2 += __shfl_xor_sync(0xffffffffu, s2, o);
            d  += __shfl_xor_sync(0xffffffffu, d,  o);
        }
        float i1 = 1.0f / fmaxf(sqrtf(s1), 1e-12f);
        float i2 = 1.0f / fmaxf(sqrtf(s2), 1e-12f);

        __half2 h0 = __floats2half2_rn(a.x * i1, a.y * i1);
        __half2 h1 = __floats2half2_rn(a.z * i1, a.w * i1);
        uint2 u;
        u.x = *(uint32_t*)&h0; u.y = *(uint32_t*)&h1;
        *(uint2*)(g_Fh + (size_t)i * CDIM + lane * 4) = u;

        __half2 g0 = __floats2half2_rn(b.x * i2, b.y * i2);
        __half2 g1 = __floats2half2_rn(b.z * i2, b.w * i2);
        u.x = *(uint32_t*)&g0; u.y = *(uint32_t*)&g1;
        *(uint2*)(g_Fh + (size_t)(i + N_HALF) * CDIM + lane * 4) = u;

        if (lane == 0) {
            float pos = (d * i1 * i2 - 1.0f) * INV_T;
            g_pos[i] = pos;
            g_pos[i + N_HALF] = pos;
        }
    }

    gbar(tid, target);

    // ---------------- Phase B: HMMA triangle tiles (R7) ----------------
    {
        uint32_t sb = smem_u32(dynsmem);
        const uint32_t bufA[2] = { sb + OFF_A0, sb + OFF_A1 };
        const uint32_t bufB[2] = { sb + OFF_B0, sb + OFF_B1 };
        float* sRow = (float*)(dynsmem + OFF_RED);       // [128][9]
        float* sCol = sRow + 128 * 9;                    // [256][2]

        const uint32_t aSel = (uint32_t)((wm * 64 + (lane & 15)) * TSTRIDE)
                            + (uint32_t)((lane >> 4) * 16);
        const uint32_t bSel = (uint32_t)((wn * 32 + (lane & 7) + ((lane >> 4) & 1) * 8) * TSTRIDE)
                            + (uint32_t)(((lane >> 3) & 1) * 16);

        auto mapIJ = [](int k, int& I, int& J2) {
            int i = 0, rem = k;
            while (rem >= 32 - (i >> 1)) { rem -= 32 - (i >> 1); i++; }
            I = i; J2 = (i >> 1) + rem;
        };
        auto issue_tile = [&](int I, int J2, int buf) {
            const char* gA = (const char*)(g_Fh + ((size_t)I << 7) * CDIM);
            const char* gB = (const char*)(g_Fh + ((size_t)J2 << 8) * CDIM);
            #pragma unroll
            for (int i = 0; i < 4; i++) {
                int idx = tid + i * 512, r = idx >> 4, c = idx & 15;
                cp16(bufA[buf] + r * TSTRIDE + c * 16, gA + r * 256 + c * 16);
            }
            #pragma unroll
            for (int i = 0; i < 8; i++) {
                int idx = tid + i * 512, r = idx >> 4, c = idx & 15;
                cp16(bufB[buf] + r * TSTRIDE + c * 16, gB + r * 256 + c * 16);
            }
            CP_COMMIT();
        };

        auto compute_tile = [&](int cur, int I, int J2) {
            const int Jblk = 2 * J2 + (wn >> 2);
            const bool active = (Jblk >= I);
            float pr[8], pc[8];
            #pragma unroll
            for (int h = 0; h < 8; h++) { pr[h] = 0.f; pc[h] = 0.f; }

            if (active) {
                uint32_t acc[4][4][2];
                #pragma unroll
                for (int mi = 0; mi < 4; mi++)
                    #pragma unroll
                    for (int ni = 0; ni < 4; ni++) {
                        acc[mi][ni][0] = 0u; acc[mi][ni][1] = 0u;
                    }
                const uint32_t aT = bufA[cur] + aSel;
                const uint32_t bT = bufB[cur] + bSel;
                #pragma unroll
                for (int ks = 0; ks < 8; ks++) {
                    uint32_t afr[4][4], bfr[2][4];
                    #pragma unroll
                    for (int mi = 0; mi < 4; mi++) {
                        uint32_t ad = aT + (uint32_t)(mi * 16 * TSTRIDE + ks * 32);
                        LDSM_X4(afr[mi][0], afr[mi][1], afr[mi][2], afr[mi][3], ad);
                    }
                    #pragma unroll
                    for (int np = 0; np < 2; np++) {
                        uint32_t bd = bT + (uint32_t)(np * 16 * TSTRIDE + ks * 32);
                        LDSM_X4(bfr[np][0], bfr[np][1], bfr[np][2], bfr[np][3], bd);
                    }
                    #pragma unroll
                    for (int mi = 0; mi < 4; mi++)
                        #pragma unroll
                        for (int ni = 0; ni < 4; ni++)
                            MMA16816H(acc[mi][ni], afr[mi],
                                      bfr[ni >> 1][(ni & 1) * 2],
                                      bfr[ni >> 1][(ni & 1) * 2 + 1]);
                }
                #pragma unroll
                for (int mi = 0; mi < 4; mi++)
                    #pragma unroll
                    for (int ni = 0; ni < 4; ni++)
                        #pragma unroll
                        for (int rg = 0; rg < 2; rg++) {
                            float2 f = __half22float2(
                                *(const __half2*)&acc[mi][ni][rg]);
                            float e0 = ex2f(fmaf(f.x, K1, -K1));
                            float e1 = ex2f(fmaf(f.y, K1, -K1));
                            pr[mi * 2 + rg] += e0 + e1;
                            pc[ni * 2]     += e0;
                            pc[ni * 2 + 1] += e1;
                        }
                if (Jblk == I) {
                    #pragma unroll
                    for (int mi = 0; mi < 4; mi++)
                        #pragma unroll
                        for (int ni = 0; ni < 4; ni++)
                            #pragma unroll
                            for (int rg = 0; rg < 2; rg++) {
                                int rT = wm * 64 + mi * 16 + (lane >> 2) + 8 * rg;
                                int cB = (wn & 3) * 32 + ni * 8 + (lane & 3) * 2;
                                if (cB == rT || cB + 1 == rT) {
                                    float2 f = __half22float2(
                                        *(const __half2*)&acc[mi][ni][rg]);
                                    float fd = (cB == rT) ? f.x : f.y;
                                    pr[mi * 2 + rg] -= ex2f(fmaf(fd, K1, -K1));
                                }
                            }
                }
            }

            #pragma unroll
            for (int h = 0; h < 8; h++) {
                pr[h] += __shfl_xor_sync(0xffffffffu, pr[h], 1);
                pr[h] += __shfl_xor_sync(0xffffffffu, pr[h], 2);
                pc[h] += __shfl_xor_sync(0xffffffffu, pc[h], 4);
                pc[h] += __shfl_xor_sync(0xffffffffu, pc[h], 8);
                pc[h] += __shfl_xor_sync(0xffffffffu, pc[h], 16);
            }
            if ((lane & 3) == 0) {
                #pragma unroll
                for (int h = 0; h < 8; h++) {
                    int r = wm * 64 + (h >> 1) * 16 + (lane >> 2) + 8 * (h & 1);
                    sRow[r * 9 + wn] = pr[h];
                }
            }
            if (lane < 4) {
                #pragma unroll
                for (int h = 0; h < 8; h++) {
                    int c = wn * 32 + (h >> 1) * 8 + lane * 2 + (h & 1);
                    sCol[c * 2 + wm] = pc[h];
                }
            }
            __syncthreads();

            const int JA = 2 * J2, JB = 2 * J2 + 1;
            if (tid < 128) {
                float vA = sRow[tid * 9 + 0] + sRow[tid * 9 + 1]
                         + sRow[tid * 9 + 2] + sRow[tid * 9 + 3];
                float vB = sRow[tid * 9 + 4] + sRow[tid * 9 + 5]
                         + sRow[tid * 9 + 6] + sRow[tid * 9 + 7];
                if (JA >= I) g_part[((size_t)I * NBLK + JA) * 128 + tid] = vA;
                g_part[((size_t)I * NBLK + JB) * 128 + tid] = vB;
            } else if (tid < 384) {
                int c  = tid - 128;
                int Jb = JA + (c >> 7);
                if (Jb > I)
                    g_part[((size_t)Jb * NBLK + I) * 128 + (c & 127)] =
                        sCol[c * 2] + sCol[c * 2 + 1];
            }
        };

        int k = bx;
        int I, J2, In, Jn;
        mapIJ(k, I, J2);
        issue_tile(I, J2, 0);
        int k1 = k + GRID;
        bool h1 = (k1 < TILES);
        if (h1) { mapIJ(k1, In, Jn); issue_tile(In, Jn, 1); CP_WAIT1(); }
        else    { CP_WAIT0(); }
        __syncthreads();

        int t = 0;
        while (true) {
            int cur = t & 1;
            compute_tile(cur, I, J2);
            if (k + GRID >= TILES) break;
            int k2 = k + 2 * GRID;
            int In2 = 0, Jn2 = 0;
            if (k2 < TILES) {
                mapIJ(k2, In2, Jn2);
                issue_tile(In2, Jn2, cur);
                CP_WAIT1();
            } else {
                CP_WAIT0();
            }
            __syncthreads();
            I = In; J2 = Jn; In = In2; Jn = Jn2;
            k += GRID; t++;
        }
    }

    gbar(tid, target);

    // ---------------- Phase C: gather + final reduction ----------------
    if (bx < 16) {
        double* sm = (double*)dynsmem;       // reuse tile smem
        int row = bx * 512 + tid;
        int R = row >> 7, m = row & 127;
        float s = 0.f;
        #pragma unroll 8
        for (int O = 0; O < NBLK; O++)
            s += g_part[((size_t)R * NBLK + O) * 128 + m];
        sm[tid] = (double)(g_pos[row] - logf(s));
        __syncthreads();
        #pragma unroll
        for (int o = 256; o; o >>= 1) {
            if (tid < o) sm[tid] += sm[tid + o];
            __syncthreads();
        }
        __shared__ int isLast;
        if (tid == 0) {
            g_bsum[bx] = sm[0];
            __threadfence();
            isLast = (atomicAdd(&g_ctr, 1) == 15);
        }
        __syncthreads();
        if (isLast && tid == 0) {
            double tot = 0.0;
            #pragma unroll
            for (int i = 0; i < 16; i++) tot += g_bsum[i];
            out[0] = (float)(-tot / (double)TWO_N);
            g_ctr = 0;   // reset for graph replay
        }
    }
}

// ---------------------------------------------------------------------------
extern "C" void kernel_launch(void* const* d_in, const int* in_sizes, int n_in,
                              void* d_out, int out_size) {
    const float* f1 = (const float*)d_in[0];
    const float* f2 = (const float*)d_in[1];
    float* out = (float*)d_out;

    cudaFuncSetAttribute(ntxent_fused_kernel,
                         cudaFuncAttributeMaxDynamicSharedMemorySize, SMEM_DYN);

    ntxent_fused_kernel<<<GRID, 512, SMEM_DYN>>>(f1, f2, out);
}